// round 4
// baseline (speedup 1.0000x reference)
#include <cuda_runtime.h>
#include <cstdint>

#define NN 50000
#define EE 800000
#define FF 602
#define HH 32
#define CC 41
typedef unsigned long long u64;

// ---------------- scratch (device globals) -----------------------------------
__device__ float g_y[NN * HH];     // x @ W1a              (gather src 1)
__device__ float g_pre1[NN * HH];  // y + b1a + agg
__device__ float g_t1[NN * HH];    // relu(pre1) @ W1b + b1b
__device__ float g_z2[NN * HH];    // t1 @ WfA + cA        (gather src 2)
__device__ float g_pre2[NN * HH];  // z2 + b2a + agg
__device__ float g_t2[NN * HH];    // relu(pre2) @ W2b + b2b
__device__ float g_stats[4 * HH];  // [sum1, sq1, sum2, sq2]
__device__ float g_WfA[HH * HH];   // diag(sc1) @ W2a
__device__ float g_WfF[HH * HH];   // diag(sc2) @ Wf1
__device__ float g_cA[HH];         // sh1 @ W2a
__device__ float g_cB[HH];         // (unused, kept for fold signature)
__device__ float g_cF[HH];         // sh2 @ Wf1 + bf1
// CSR machinery
__device__ int g_cnt[NN + 1];
__device__ int g_off[NN + 1];
__device__ int g_cur[NN];
__device__ int g_csr[EE];
__device__ int g_bsum[64];

__device__ __forceinline__ u64 fdup(float v) {
    u64 d; unsigned u = __float_as_uint(v);
    asm("mov.b64 %0, {%1,%1};" : "=l"(d) : "r"(u));
    return d;
}
__device__ __forceinline__ float2 u2f(u64 v) {
    unsigned lo, hi;
    asm("mov.b64 {%0,%1}, %2;" : "=r"(lo), "=r"(hi) : "l"(v));
    return make_float2(__uint_as_float(lo), __uint_as_float(hi));
}
__device__ __forceinline__ void ffma2(u64& a, u64 x, u64 w) {
    asm("fma.rn.f32x2 %0, %1, %2, %0;" : "+l"(a) : "l"(x), "l"(w));
}

// ---------------- CSR build --------------------------------------------------
__global__ void zero_kernel(int nel) {
    int i = blockIdx.x * blockDim.x + threadIdx.x;
    if (i < nel) g_cnt[i] = 0;
    if (i < 4 * HH) g_stats[i] = 0.f;
}

__global__ void count_kernel(const int* __restrict__ row, int E) {
    int e = blockIdx.x * blockDim.x + threadIdx.x;
    if (e < E) atomicAdd(&g_cnt[row[e]], 1);
}

__global__ void scan1_kernel(int nel) {
    __shared__ int s[1024];
    int t = threadIdx.x;
    int i = blockIdx.x * 1024 + t;
    int v = (i < nel) ? g_cnt[i] : 0;
    s[t] = v;
    __syncthreads();
#pragma unroll
    for (int d = 1; d < 1024; d <<= 1) {
        int a = (t >= d) ? s[t - d] : 0;
        __syncthreads();
        s[t] += a;
        __syncthreads();
    }
    if (i < nel) g_off[i] = s[t] - v;  // exclusive
    if (t == 1023) g_bsum[blockIdx.x] = s[1023];
}

__global__ void scan2_kernel(int nb) {
    __shared__ int s[64];
    int t = threadIdx.x;
    int v = (t < nb) ? g_bsum[t] : 0;
    s[t] = v;
    __syncthreads();
#pragma unroll
    for (int d = 1; d < 64; d <<= 1) {
        int a = (t >= d) ? s[t - d] : 0;
        __syncthreads();
        s[t] += a;
        __syncthreads();
    }
    if (t < nb) g_bsum[t] = s[t] - v;  // exclusive block offsets
}

__global__ void scan3_kernel(int nel, int nrows) {
    int i = blockIdx.x * 1024 + threadIdx.x;
    if (i < nel) {
        int o = g_off[i] + g_bsum[blockIdx.x];
        g_off[i] = o;
        if (i < nrows) g_cur[i] = o;
    }
}

__global__ void place_kernel(const int* __restrict__ row,
                             const int* __restrict__ col, int E) {
    int e = blockIdx.x * blockDim.x + threadIdx.x;
    if (e < E) {
        int r = row[e];
        int p = atomicAdd(&g_cur[r], 1);
        g_csr[p] = col[e];
    }
}

// ---------------- K1: y = x @ W1a (no bias; agg adds it) ---------------------
// 128 rows x 32 cols per block, 128 threads. Thread = 8 rows x 4 cols.
// X natural (row-pairs read as native f32x2), W duplicated (w,w).
__global__ __launch_bounds__(128) void gemm_x_kernel(
    const float* __restrict__ x, const float* __restrict__ W, int nrows) {
    __shared__ __align__(16) float Xs[32][132];
    __shared__ __align__(16) u64 Wd[32][32];
    int tid = threadIdx.x, cg = tid & 7, rg = tid >> 3;
    int row0 = blockIdx.x * 128;

    u64 acc[4][4];
#pragma unroll
    for (int i = 0; i < 4; i++)
#pragma unroll
        for (int j = 0; j < 4; j++) acc[i][j] = 0ULL;

    for (int k0 = 0; k0 < FF; k0 += 32) {
        for (int i = tid; i < 1024; i += 128) {
            int k = i >> 5, c = i & 31;
            int gk = k0 + k;
            float w = (gk < FF) ? W[gk * HH + c] : 0.f;
            Wd[k][c] = fdup(w);
        }
        for (int i = tid; i < 2048; i += 128) {
            int r = i >> 4, q = i & 15;
            int gr = row0 + r, gk = k0 + 2 * q;
            float2 v = make_float2(0.f, 0.f);
            if (gr < nrows && gk < FF) {
                if (gk + 1 < FF) v = *(const float2*)&x[(size_t)gr * FF + gk];
                else v.x = x[(size_t)gr * FF + gk];
            }
            Xs[2 * q][r] = v.x;
            Xs[2 * q + 1][r] = v.y;
        }
        __syncthreads();
#pragma unroll
        for (int k = 0; k < 32; k++) {
            ulonglong2 xa = *(const ulonglong2*)&Xs[k][rg * 8];
            ulonglong2 xb = *(const ulonglong2*)&Xs[k][rg * 8 + 4];
            ulonglong2 wa = *(const ulonglong2*)&Wd[k][4 * cg];
            ulonglong2 wb = *(const ulonglong2*)&Wd[k][4 * cg + 2];
            u64 xp[4] = {xa.x, xa.y, xb.x, xb.y};
            u64 wp[4] = {wa.x, wa.y, wb.x, wb.y};
#pragma unroll
            for (int i = 0; i < 4; i++)
#pragma unroll
                for (int j = 0; j < 4; j++) ffma2(acc[i][j], xp[i], wp[j]);
        }
        __syncthreads();
    }

#pragma unroll
    for (int i = 0; i < 4; i++) {
        float2 v0 = u2f(acc[i][0]), v1 = u2f(acc[i][1]);
        float2 v2 = u2f(acc[i][2]), v3 = u2f(acc[i][3]);
        int r0 = row0 + rg * 8 + 2 * i;
        if (r0 < nrows)
            *(float4*)&g_y[(size_t)r0 * HH + 4 * cg] =
                make_float4(v0.x, v1.x, v2.x, v3.x);
        if (r0 + 1 < nrows)
            *(float4*)&g_y[(size_t)(r0 + 1) * HH + 4 * cg] =
                make_float4(v0.y, v1.y, v2.y, v3.y);
    }
}

// ---------------- aggregation: dst[r] = src[r] + bias + sum_nb src[c] --------
__global__ __launch_bounds__(256) void agg_kernel(
    const float* __restrict__ bias, int phase, int nrows) {
    int gt = blockIdx.x * 256 + threadIdx.x;
    int w = gt >> 5, lane = gt & 31;
    if (w >= nrows) return;
    const float* __restrict__ src = phase ? g_z2 : g_y;
    float* __restrict__ dst = phase ? g_pre2 : g_pre1;
    int beg = g_off[w], end = g_off[w + 1];
    float a0 = src[(size_t)w * HH + lane] + bias[lane];
    float a1 = 0.f, a2 = 0.f, a3 = 0.f;
    int j = beg;
    for (; j + 4 <= end; j += 4) {
        int c0 = __ldg(&g_csr[j]);
        int c1 = __ldg(&g_csr[j + 1]);
        int c2 = __ldg(&g_csr[j + 2]);
        int c3 = __ldg(&g_csr[j + 3]);
        a0 += src[(size_t)c0 * HH + lane];
        a1 += src[(size_t)c1 * HH + lane];
        a2 += src[(size_t)c2 * HH + lane];
        a3 += src[(size_t)c3 * HH + lane];
    }
    for (; j < end; j++) {
        int c = __ldg(&g_csr[j]);
        a0 += src[(size_t)c * HH + lane];
    }
    dst[(size_t)w * HH + lane] = (a0 + a1) + (a2 + a3);
}

// ---------------- shared K=32 GEMM core (X dup layout, proven) ---------------
__device__ __forceinline__ void stage_and_mm32(
    const float* __restrict__ in, const float* __restrict__ Wsrc, int relu_in,
    int nrows, int row0, int tid, int cg, int rg,
    u64 (*Xd)[130], u64 (*Ws)[16], u64 acc[8][2]) {
    const float4* Wv = (const float4*)Wsrc;
    for (int i = tid; i < 256; i += 128)
        ((float4*)&Ws[i >> 3][0])[i & 7] = Wv[i];
    for (int i = tid; i < 32 * 128; i += 128) {
        int k = i & 31, r = i >> 5;
        int gr = row0 + r;
        float v = (gr < nrows) ? in[(size_t)gr * HH + k] : 0.f;
        if (relu_in) v = fmaxf(v, 0.f);
        Xd[k][r] = fdup(v);
    }
    __syncthreads();
#pragma unroll
    for (int k = 0; k < 32; k++) {
        u64 xv[8];
#pragma unroll
        for (int h = 0; h < 4; h++)
            *(ulonglong2*)&xv[2 * h] = *(const ulonglong2*)&Xd[k][rg * 8 + 2 * h];
        ulonglong2 wv = *(const ulonglong2*)&Ws[k][cg * 2];
#pragma unroll
        for (int i = 0; i < 8; i++) {
            ffma2(acc[i][0], xv[i], wv.x);
            ffma2(acc[i][1], xv[i], wv.y);
        }
    }
}

// ---------------- K3/K6: t = relu(pre) @ W + b ; BN stats --------------------
__global__ __launch_bounds__(128) void mlp_kernel(
    const float* __restrict__ W, const float* __restrict__ b, int phase, int nrows) {
    __shared__ __align__(16) u64 Xd[32][130];
    __shared__ __align__(16) u64 Ws[32][16];
    const float* in = phase ? g_pre2 : g_pre1;
    float* out = phase ? g_t2 : g_t1;
    int soff = phase ? 2 * HH : 0;
    int tid = threadIdx.x, cg = tid & 7, rg = tid >> 3;
    int row0 = blockIdx.x * 128;
    u64 acc[8][2];
#pragma unroll
    for (int i = 0; i < 8; i++) { acc[i][0] = 0; acc[i][1] = 0; }
    stage_and_mm32(in, W, 1, nrows, row0, tid, cg, rg, Xd, Ws, acc);

    float2 b0 = *(const float2*)&b[4 * cg];
    float2 b1 = *(const float2*)&b[4 * cg + 2];
    float s0 = 0, s1 = 0, s2 = 0, s3 = 0, q0 = 0, q1 = 0, q2 = 0, q3 = 0;
#pragma unroll
    for (int i = 0; i < 8; i++) {
        int r = row0 + rg * 8 + i;
        if (r < nrows) {
            float2 v0 = u2f(acc[i][0]); v0.x += b0.x; v0.y += b0.y;
            float2 v1 = u2f(acc[i][1]); v1.x += b1.x; v1.y += b1.y;
            *(float2*)&out[(size_t)r * HH + 4 * cg] = v0;
            *(float2*)&out[(size_t)r * HH + 4 * cg + 2] = v1;
            s0 += v0.x; q0 += v0.x * v0.x; s1 += v0.y; q1 += v0.y * v0.y;
            s2 += v1.x; q2 += v1.x * v1.x; s3 += v1.y; q3 += v1.y * v1.y;
        }
    }
    __syncthreads();
    float* sb = (float*)Xd;
    int c0 = 4 * cg;
    sb[rg * 32 + c0] = s0;       sb[rg * 32 + c0 + 1] = s1;
    sb[rg * 32 + c0 + 2] = s2;   sb[rg * 32 + c0 + 3] = s3;
    sb[512 + rg * 32 + c0] = q0;     sb[512 + rg * 32 + c0 + 1] = q1;
    sb[512 + rg * 32 + c0 + 2] = q2; sb[512 + rg * 32 + c0 + 3] = q3;
    __syncthreads();
    if (tid < 64) {
        int c = tid & 31, which = tid >> 5;
        float t = 0.f;
#pragma unroll
        for (int g2 = 0; g2 < 16; g2++) t += sb[which * 512 + g2 * 32 + c];
        atomicAdd(&g_stats[soff + which * HH + c], t);
    }
}

// ---------------- fold: BN into next weight matrix ---------------------------
__global__ void fold_kernel(const float* __restrict__ W, const float* __restrict__ g,
                            const float* __restrict__ be, const float* __restrict__ badd,
                            float* __restrict__ Wout, float* __restrict__ c0,
                            float* __restrict__ c1, int soff, float invn) {
    __shared__ float sc[HH], sh[HH], prod[HH][HH + 1];
    int tid = threadIdx.x;  // 1024
    int k = tid >> 5, c = tid & 31;
    if (tid < HH) {
        float m = g_stats[soff + tid] * invn;
        float v = g_stats[soff + HH + tid] * invn - m * m;
        float s = rsqrtf(v + 1e-5f) * g[tid];
        sc[tid] = s;
        sh[tid] = be[tid] - m * s;
    }
    __syncthreads();
    float w = W[k * HH + c];
    Wout[k * HH + c] = sc[k] * w;
    prod[k][c] = sh[k] * w;
    __syncthreads();
    if (tid < HH) {
        float s = 0.f;
#pragma unroll
        for (int kk = 0; kk < HH; kk++) s += prod[kk][tid];
        if (c0) c0[tid] = s;
        c1[tid] = s + badd[tid];
    }
}

// ---------------- K4: z2 = t1 @ WfA + cA -------------------------------------
__global__ __launch_bounds__(128) void gemmb_kernel(int nrows) {
    __shared__ __align__(16) u64 Xd[32][130];
    __shared__ __align__(16) u64 Ws[32][16];
    int tid = threadIdx.x, cg = tid & 7, rg = tid >> 3;
    int row0 = blockIdx.x * 128;
    u64 acc[8][2];
#pragma unroll
    for (int i = 0; i < 8; i++) { acc[i][0] = 0; acc[i][1] = 0; }
    stage_and_mm32(g_t1, g_WfA, 0, nrows, row0, tid, cg, rg, Xd, Ws, acc);
    float2 a0 = *(const float2*)&g_cA[4 * cg];
    float2 a1 = *(const float2*)&g_cA[4 * cg + 2];
#pragma unroll
    for (int i = 0; i < 8; i++) {
        int r = row0 + rg * 8 + i;
        if (r < nrows) {
            float2 v0 = u2f(acc[i][0]);
            float2 v1 = u2f(acc[i][1]);
            *(float2*)&g_z2[(size_t)r * HH + 4 * cg] = make_float2(v0.x + a0.x, v0.y + a0.y);
            *(float2*)&g_z2[(size_t)r * HH + 4 * cg + 2] = make_float2(v1.x + a1.x, v1.y + a1.y);
        }
    }
}

// ---------------- K7: f = relu(t2 @ WfF + cF) ; out = f @ Wf2 + bf2 ----------
__global__ __launch_bounds__(128) void final_kernel(
    const float* __restrict__ Wf2, const float* __restrict__ bf2,
    float* __restrict__ out, int nrows) {
    __shared__ __align__(16) u64 Xd[32][130];
    __shared__ __align__(16) u64 Ws[32][16];
    __shared__ __align__(16) u64 W2[32][24];
    int tid = threadIdx.x, cg = tid & 7, rg = tid >> 3;
    int row0 = blockIdx.x * 128;

    float* W2f = (float*)W2;
    for (int i = tid; i < 32 * 48; i += 128) {
        int k = i / 48, c = i - k * 48;
        W2f[k * 48 + c] = (c < CC) ? Wf2[k * CC + c] : 0.f;
    }

    u64 acc[8][2];
#pragma unroll
    for (int i = 0; i < 8; i++) { acc[i][0] = 0; acc[i][1] = 0; }
    stage_and_mm32(g_t2, g_WfF, 0, nrows, row0, tid, cg, rg, Xd, Ws, acc);

    float2 cf0 = *(const float2*)&g_cF[4 * cg];
    float2 cf1 = *(const float2*)&g_cF[4 * cg + 2];
    __syncthreads();
#pragma unroll
    for (int i = 0; i < 8; i++) {
        int r = rg * 8 + i;
        float2 v0 = u2f(acc[i][0]);
        float2 v1 = u2f(acc[i][1]);
        Xd[4 * cg][r]     = fdup(fmaxf(v0.x + cf0.x, 0.f));
        Xd[4 * cg + 1][r] = fdup(fmaxf(v0.y + cf0.y, 0.f));
        Xd[4 * cg + 2][r] = fdup(fmaxf(v1.x + cf1.x, 0.f));
        Xd[4 * cg + 3][r] = fdup(fmaxf(v1.y + cf1.y, 0.f));
    }
    __syncthreads();

    u64 acc2[8][3];
#pragma unroll
    for (int i = 0; i < 8; i++) { acc2[i][0] = 0; acc2[i][1] = 0; acc2[i][2] = 0; }
#pragma unroll
    for (int k = 0; k < 32; k++) {
        u64 xv[8];
#pragma unroll
        for (int h = 0; h < 4; h++)
            *(ulonglong2*)&xv[2 * h] = *(const ulonglong2*)&Xd[k][rg * 8 + 2 * h];
        u64 w0 = W2[k][cg * 3], w1 = W2[k][cg * 3 + 1], w2 = W2[k][cg * 3 + 2];
#pragma unroll
        for (int i = 0; i < 8; i++) {
            ffma2(acc2[i][0], xv[i], w0);
            ffma2(acc2[i][1], xv[i], w1);
            ffma2(acc2[i][2], xv[i], w2);
        }
    }

    float bb[6];
#pragma unroll
    for (int j = 0; j < 3; j++) {
        int c = 2 * (cg * 3 + j);
        bb[2 * j]     = (c < CC)     ? bf2[c]     : 0.f;
        bb[2 * j + 1] = (c + 1 < CC) ? bf2[c + 1] : 0.f;
    }
#pragma unroll
    for (int i = 0; i < 8; i++) {
        int r = row0 + rg * 8 + i;
        if (r < nrows) {
#pragma unroll
            for (int j = 0; j < 3; j++) {
                int c = 2 * (cg * 3 + j);
                float2 v = u2f(acc2[i][j]);
                if (c < CC)     out[(size_t)r * CC + c]     = v.x + bb[2 * j];
                if (c + 1 < CC) out[(size_t)r * CC + c + 1] = v.y + bb[2 * j + 1];
            }
        }
    }
}

// ---------------- launch -----------------------------------------------------
extern "C" void kernel_launch(void* const* d_in, const int* in_sizes, int n_in,
                              void* d_out, int out_size) {
    const float* x   = (const float*)d_in[0];
    const int*   row = (const int*)d_in[1];
    const int*   col = (const int*)d_in[2];
    const float* W1a = (const float*)d_in[3];
    const float* b1a = (const float*)d_in[4];
    const float* W1b = (const float*)d_in[5];
    const float* b1b = (const float*)d_in[6];
    const float* g1  = (const float*)d_in[7];
    const float* be1 = (const float*)d_in[8];
    const float* W2a = (const float*)d_in[9];
    const float* b2a = (const float*)d_in[10];
    const float* W2b = (const float*)d_in[11];
    const float* b2b = (const float*)d_in[12];
    const float* g2  = (const float*)d_in[13];
    const float* be2 = (const float*)d_in[14];
    const float* Wf1 = (const float*)d_in[15];
    const float* bf1 = (const float*)d_in[16];
    const float* Wf2 = (const float*)d_in[17];
    const float* bf2 = (const float*)d_in[18];
    float* out = (float*)d_out;

    int nrows = in_sizes[0] / FF;
    int E = in_sizes[1];
    float invn = 1.f / (float)nrows;
    int g128 = (nrows + 127) / 128;
    int nel = nrows + 1;
    int nsb = (nel + 1023) / 1024;

    float *d_WfA, *d_WfF, *d_cA, *d_cB, *d_cF;
    cudaGetSymbolAddress((void**)&d_WfA, g_WfA);
    cudaGetSymbolAddress((void**)&d_WfF, g_WfF);
    cudaGetSymbolAddress((void**)&d_cA, g_cA);
    cudaGetSymbolAddress((void**)&d_cB, g_cB);
    cudaGetSymbolAddress((void**)&d_cF, g_cF);

    // CSR build
    zero_kernel<<<(nel + 255) / 256, 256>>>(nel);
    count_kernel<<<(E + 255) / 256, 256>>>(row, E);
    scan1_kernel<<<nsb, 1024>>>(nel);
    scan2_kernel<<<1, 64>>>(nsb);
    scan3_kernel<<<nsb, 1024>>>(nel, nrows);
    place_kernel<<<(E + 255) / 256, 256>>>(row, col, E);

    // pipeline
    gemm_x_kernel<<<g128, 128>>>(x, W1a, nrows);
    agg_kernel<<<(nrows * 32 + 255) / 256, 256>>>(b1a, 0, nrows);
    mlp_kernel<<<g128, 128>>>(W1b, b1b, 0, nrows);
    fold_kernel<<<1, 1024>>>(W2a, g1, be1, b2a, d_WfA, d_cA, d_cB, 0, invn);
    gemmb_kernel<<<g128, 128>>>(nrows);
    agg_kernel<<<(nrows * 32 + 255) / 256, 256>>>(b2a, 1, nrows);
    mlp_kernel<<<g128, 128>>>(W2b, b2b, 1, nrows);
    fold_kernel<<<1, 1024>>>(Wf1, g2, be2, bf1, d_WfF, (float*)0, d_cF, 2 * HH, invn);
    final_kernel<<<g128, 128>>>(Wf2, bf2, out, nrows);
}